// round 7
// baseline (speedup 1.0000x reference)
#include <cuda_runtime.h>
#include <math.h>

#define TT 1500
#define BB 16
#define DD 512
#define HH 1024
#define KEEPF 0.8f
#define EPSF 1e-5f
#define NTOT (TT*BB*HH)
#define GRID_SCAN 128
#define REDS 65                     // padded red row stride (u64)
#define FPAD 32                     // ints per flag slot (128B)

typedef unsigned long long u64;

#define FMA2(d,a,b,c) asm("fma.rn.f32x2 %0, %1, %2, %3;" : "=l"(d) : "l"(a), "l"(b), "l"(c))
#define ADD2(d,a,b)   asm("add.rn.f32x2 %0, %1, %2;" : "=l"(d) : "l"(a), "l"(b))
#define PACK2(d,lo,hi) asm("mov.b64 %0, {%1, %2};" : "=l"(d) : "f"(lo), "f"(hi))
#define UNPACK2(lo,hi,in) asm("mov.b64 {%0, %1}, %2;" : "=f"(lo), "=f"(hi) : "l"(in))
#define CPA_COMMIT() asm volatile("cp.async.commit_group;" ::: "memory")
#define CPA_WAIT(n)  asm volatile("cp.async.wait_group %0;" :: "n"(n) : "memory")

// -------- scratch (device globals: no allocation allowed) --------
__device__ float g_wh[NTOT];
__device__ float g_wz[NTOT];
__device__ float g_h0[NTOT];
__device__ float g_hT[4*BB*HH];        // double-buffered h, 2 per layer
__device__ int   g_flags[2*GRID_SCAN*FPAD];

// =================================================================
__global__ void init_kernel(const int* __restrict__ x_len,
                            float* __restrict__ out, int out_size)
{
    int i = blockIdx.x * blockDim.x + threadIdx.x;
    if (i < 2*GRID_SCAN*FPAD) g_flags[i] = 0;
    if (i < BB*HH) {                      // zero the t=0 source buffers
        g_hT[i] = 0.f;                    // layer-0 buffer A
        g_hT[2*BB*HH + i] = 0.f;          // layer-1 buffer A
    }
    if (out_size >= NTOT + BB && i < BB) out[NTOT + i] = (float)x_len[i];
}

// =================================================================
// fused GEMM + eval BatchNorm (unchanged, fp32x2-packed, dbl-buffer)
// =================================================================
__global__ void __launch_bounds__(256) gemm_bn_kernel(
    const float* __restrict__ A, const float* __restrict__ W,
    float* __restrict__ C,
    const float* __restrict__ gam, const float* __restrict__ bet,
    const float* __restrict__ mu,  const float* __restrict__ var,
    int K)
{
    __shared__ float Asd[2][8][132];
    __shared__ float Bs[2][8][132];

    int tid = threadIdx.x;
    int m0 = blockIdx.y * 64;
    int n0 = blockIdx.x * 128;

    int arow = tid >> 2;
    int acol = (tid & 3) * 2;
    int brow = tid >> 1;
    int bcol = (tid & 1) * 4;

    const float* Ap = A + (size_t)(m0 + arow) * K + acol;
    const float* Wp = W + (size_t)(n0 + brow) * K + bcol;

    float2 ar = *(const float2*)Ap;
    float4 br = *(const float4*)Wp;

    u64 acc[4][4];
    #pragma unroll
    for (int i = 0; i < 4; i++)
        #pragma unroll
        for (int j = 0; j < 4; j++) acc[i][j] = 0ull;

    int tx = tid & 15, ty = tid >> 4;
    int am2 = ty * 8;
    int bn  = tx * 8;
    int nk = K >> 3;

    for (int kt = 0; kt < nk; kt++) {
        int p = kt & 1;
        Asd[p][acol  ][2*arow] = ar.x;  Asd[p][acol  ][2*arow+1] = ar.x;
        Asd[p][acol+1][2*arow] = ar.y;  Asd[p][acol+1][2*arow+1] = ar.y;
        Bs[p][bcol  ][brow] = br.x;
        Bs[p][bcol+1][brow] = br.y;
        Bs[p][bcol+2][brow] = br.z;
        Bs[p][bcol+3][brow] = br.w;
        if (kt + 1 < nk) {
            ar = *(const float2*)(Ap + (size_t)(kt+1)*8);
            br = *(const float4*)(Wp + (size_t)(kt+1)*8);
        }
        __syncthreads();
        #pragma unroll
        for (int kk = 0; kk < 8; kk++) {
            ulonglong2 a01 = *(const ulonglong2*)&Asd[p][kk][am2];
            ulonglong2 a23 = *(const ulonglong2*)&Asd[p][kk][am2+4];
            ulonglong2 b01 = *(const ulonglong2*)&Bs[p][kk][bn];
            ulonglong2 b23 = *(const ulonglong2*)&Bs[p][kk][bn+4];
            u64 av[4] = {a01.x, a01.y, a23.x, a23.y};
            u64 bv[4] = {b01.x, b01.y, b23.x, b23.y};
            #pragma unroll
            for (int i = 0; i < 4; i++)
                #pragma unroll
                for (int j = 0; j < 4; j++)
                    FMA2(acc[i][j], av[i], bv[j], acc[i][j]);
        }
    }

    float sc[8], sh[8];
    #pragma unroll
    for (int j = 0; j < 8; j++) {
        int n = n0 + bn + j;
        float inv = rsqrtf(var[n] + EPSF);
        sc[j] = gam[n] * inv;
        sh[j] = bet[n] - mu[n] * sc[j];
    }
    u64 sc2[4], sh2[4];
    #pragma unroll
    for (int j = 0; j < 4; j++) {
        PACK2(sc2[j], sc[2*j], sc[2*j+1]);
        PACK2(sh2[j], sh[2*j], sh[2*j+1]);
    }
    #pragma unroll
    for (int i = 0; i < 4; i++) {
        size_t row = (size_t)(m0 + ty*4 + i) * HH + n0 + bn;
        u64 o[4];
        #pragma unroll
        for (int j = 0; j < 4; j++) FMA2(o[j], acc[i][j], sc2[j], sh2[j]);
        ulonglong2 s0; s0.x = o[0]; s0.y = o[1];
        ulonglong2 s1; s1.x = o[2]; s1.y = o[3];
        *(ulonglong2*)(C + row)     = s0;
        *(ulonglong2*)(C + row + 4) = s1;
    }
}

// =================================================================
// persistent liGRU scan v5: NO full-grid barrier.
// h exchanged in 16 chunks of 64 cols; chunk c produced by CTAs
// 8c..8c+7 (per-CTA MONOTONE flag).  Consumer streams 4 super-chunks
// (cp.async.cg, rotated so own group comes first) overlapped with
// FMA compute.  Double-buffered hT makes the protocol race-free:
// flag(t+1) implies that CTA finished READING buffer(t), so writes
// of h_{t+2} into buffer(t) can never pass unread data.
// =================================================================
__global__ void __launch_bounds__(256, 1) scan_kernel(
    const float* __restrict__ WH, const float* __restrict__ WZ,
    const float* __restrict__ Uh, const float* __restrict__ Uz,
    float* __restrict__ Hout,
    float* __restrict__ hTa, float* __restrict__ hTb,
    int* __restrict__ flags)
{
    extern __shared__ float smem[];
    float* hs  = smem;                       // [16][1024] h_{t-1}, global-k layout
    u64*   red = (u64*)(smem + BB*HH);       // [128][REDS]

    int tid = threadIdx.x;
    int qd  = tid >> 7;            // 0..1 quad
    int bh  = (tid >> 6) & 1;      // 0..1 batch-half
    int kg  = tid & 63;            // 0..63 k-slice within a chunk
    int j0  = blockIdx.x * 8;
    int start = (blockIdx.x >> 3) & ~3;   // rotation: own chunk in 1st super-chunk

    // ---- stationary U in registers, PERMUTED by chunk rotation ----
    // slot s holds chunk (start+s)&15
    u64 uz[2][16], uh[2][16];
    #pragma unroll
    for (int pr = 0; pr < 2; pr++) {
        const float* z0 = Uz + (size_t)(j0 + qd*4 + 2*pr)*HH;
        const float* z1 = z0 + HH;
        const float* a0 = Uh + (size_t)(j0 + qd*4 + 2*pr)*HH;
        const float* a1 = a0 + HH;
        #pragma unroll
        for (int s = 0; s < 16; s++) {
            int k = (((start + s) & 15) << 6) + kg;
            PACK2(uz[pr][s], z0[k], z1[k]);
            PACK2(uh[pr][s], a0[k], a1[k]);
        }
    }

    int r_b   = tid & 15;
    int r_grp = tid >> 4;
    int r_m   = r_grp & 1;
    int g_qd  = (r_grp >> 2) & 1;
    int g_pr  = (r_grp >> 1) & 1;
    int jg    = j0 + g_qd*4 + g_pr*2;
    bool is_red  = (tid < 128);
    bool is_gate = is_red && (r_m == 0);

    // stage mapping: thread stages one float4 per chunk
    int st_b = tid >> 4;           // batch 0..15
    int st_x = (tid & 15) << 2;    // float offset within 64-col chunk

    // flag this thread spins on per super-chunk: one of 32 producers
    int sp_q = (tid >> 3) & 3;     // chunk-within-superchunk
    int sp_c = tid & 7;            // producer CTA within chunk
    __syncthreads();

    for (int t = 0; t < TT; t++) {
        const float* cur = (t & 1) ? hTb : hTa;
        float*       nxt = (t & 1) ? hTa : hTb;

        // prefetch pre-projections (gate threads), hidden behind pipeline
        float2 wz2 = make_float2(0.f, 0.f), wh2 = wz2;
        size_t ob = 0;
        if (is_gate) {
            ob = ((size_t)t*BB + r_b)*HH + jg;
            wz2 = *(const float2*)(WZ + ob);
            wh2 = *(const float2*)(WH + ob);
        }

        u64 az[2][8], ah[2][8];
        #pragma unroll
        for (int pr = 0; pr < 2; pr++)
            #pragma unroll
            for (int b = 0; b < 8; b++) { az[pr][b] = 0ull; ah[pr][b] = 0ull; }

        // ---- wait producers of super-chunk sc, then cp.async its 16KB ----
        #define WAIT_SC(sc) { \
            int c_ = (start + (sc)*4 + sp_q) & 15; \
            const int* fp_ = flags + (8*c_ + sp_c)*FPAD; \
            int v_; \
            do { asm volatile("ld.acquire.gpu.global.s32 %0, [%1];" \
                              : "=r"(v_) : "l"(fp_) : "memory"); } while (v_ < t); }

        #define STAGE_SC(sc) { \
            _Pragma("unroll") \
            for (int q_ = 0; q_ < 4; q_++) { \
                int c_ = (start + (sc)*4 + q_) & 15; \
                const float* src_ = cur + st_b*HH + (c_<<6) + st_x; \
                unsigned dst_ = (unsigned)__cvta_generic_to_shared(hs + st_b*HH + (c_<<6) + st_x); \
                asm volatile("cp.async.cg.shared.global [%0], [%1], 16;" \
                             :: "r"(dst_), "l"(src_) : "memory"); \
            } \
            CPA_COMMIT(); }

        #define COMP_SLOT(s) { \
            int c_ = (start + (s)) & 15; \
            const float* hk_ = hs + (bh<<3)*HH + (c_<<6) + kg; \
            _Pragma("unroll") \
            for (int b = 0; b < 8; b++) { \
                float hv_ = hk_[b*HH]; \
                u64 hd_; PACK2(hd_, hv_, hv_); \
                FMA2(az[0][b], hd_, uz[0][s], az[0][b]); \
                FMA2(ah[0][b], hd_, uh[0][s], ah[0][b]); \
                FMA2(az[1][b], hd_, uz[1][s], az[1][b]); \
                FMA2(ah[1][b], hd_, uh[1][s], ah[1][b]); \
            } }

        WAIT_SC(0); STAGE_SC(0);
        WAIT_SC(1); STAGE_SC(1);
        CPA_WAIT(1); __syncthreads();
        COMP_SLOT(0); COMP_SLOT(1); COMP_SLOT(2); COMP_SLOT(3);
        WAIT_SC(2); STAGE_SC(2);
        CPA_WAIT(1); __syncthreads();
        COMP_SLOT(4); COMP_SLOT(5); COMP_SLOT(6); COMP_SLOT(7);
        WAIT_SC(3); STAGE_SC(3);
        CPA_WAIT(1); __syncthreads();
        COMP_SLOT(8); COMP_SLOT(9); COMP_SLOT(10); COMP_SLOT(11);
        CPA_WAIT(0); __syncthreads();
        COMP_SLOT(12); COMP_SLOT(13); COMP_SLOT(14); COMP_SLOT(15);

        // ---- k-partial write: red[grp*16 + b][kg] ----
        {
            u64* rp = red + kg;
            #pragma unroll
            for (int pr = 0; pr < 2; pr++)
                #pragma unroll
                for (int b = 0; b < 8; b++) {
                    int bb = (bh << 3) + b;
                    rp[((qd*4 + pr*2    )*16 + bb)*REDS] = az[pr][b];
                    rp[((qd*4 + pr*2 + 1)*16 + bb)*REDS] = ah[pr][b];
                }
        }
        __syncthreads();

        // ---- 4-warp reduce + partner exchange + gate ----
        if (is_red) {
            const u64* rr = red + (size_t)tid*REDS;
            u64 s0 = 0ull, s1 = 0ull, s2 = 0ull, s3 = 0ull;
            #pragma unroll
            for (int i = 0; i < 64; i += 4) {
                ADD2(s0, s0, rr[i]);
                ADD2(s1, s1, rr[i+1]);
                ADD2(s2, s2, rr[i+2]);
                ADD2(s3, s3, rr[i+3]);
            }
            ADD2(s0, s0, s1);
            ADD2(s2, s2, s3);
            ADD2(s0, s0, s2);
            u64 part = __shfl_xor_sync(0xffffffffu, s0, 16);
            if (is_gate) {
                float z0, z1, a0, a1;
                UNPACK2(z0, z1, s0);
                UNPACK2(a0, a1, part);
                float zt0 = 1.f / (1.f + __expf(-(wz2.x + z0)));
                float zt1 = 1.f / (1.f + __expf(-(wz2.y + z1)));
                float hc0 = fmaxf(wh2.x + a0, 0.f) * KEEPF;
                float hc1 = fmaxf(wh2.y + a1, 0.f) * KEEPF;
                float2 ho = *(const float2*)(hs + r_b*HH + jg);
                float2 hn;
                hn.x = zt0*ho.x + (1.f - zt0)*hc0;
                hn.y = zt1*ho.y + (1.f - zt1)*hc1;
                *(float2*)(Hout + ob)         = hn;
                *(float2*)(nxt + r_b*HH + jg) = hn;
            }
        }
        __syncthreads();          // gate writes + hs reads complete

        if (t == TT-1) break;
        if (tid == 0) {
            asm volatile("st.release.gpu.global.s32 [%0], %1;"
                         :: "l"(flags + blockIdx.x*FPAD), "r"(t+1) : "memory");
        }
        #undef WAIT_SC
        #undef STAGE_SC
        #undef COMP_SLOT
    }
}

// =================================================================
extern "C" void kernel_launch(void* const* d_in, const int* in_sizes, int n_in,
                              void* d_out, int out_size)
{
    const float* x     = (const float*)d_in[0];
    const int*   x_len = (const int*)  d_in[1];
    const float* whW0  = (const float*)d_in[2];
    const float* wzW0  = (const float*)d_in[3];
    const float* uhW0  = (const float*)d_in[4];
    const float* uzW0  = (const float*)d_in[5];
    const float* bnh_g0 = (const float*)d_in[6];
    const float* bnh_b0 = (const float*)d_in[7];
    const float* bnh_m0 = (const float*)d_in[8];
    const float* bnh_v0 = (const float*)d_in[9];
    const float* bnz_g0 = (const float*)d_in[10];
    const float* bnz_b0 = (const float*)d_in[11];
    const float* bnz_m0 = (const float*)d_in[12];
    const float* bnz_v0 = (const float*)d_in[13];
    const float* whW1  = (const float*)d_in[14];
    const float* wzW1  = (const float*)d_in[15];
    const float* uhW1  = (const float*)d_in[16];
    const float* uzW1  = (const float*)d_in[17];
    const float* bnh_g1 = (const float*)d_in[18];
    const float* bnh_b1 = (const float*)d_in[19];
    const float* bnh_m1 = (const float*)d_in[20];
    const float* bnh_v1 = (const float*)d_in[21];
    const float* bnz_g1 = (const float*)d_in[22];
    const float* bnz_b1 = (const float*)d_in[23];
    const float* bnz_m1 = (const float*)d_in[24];
    const float* bnz_v1 = (const float*)d_in[25];

    float* out = (float*)d_out;

    float *p_wh, *p_wz, *p_h0, *p_hT; int* p_fl;
    cudaGetSymbolAddress((void**)&p_wh, g_wh);
    cudaGetSymbolAddress((void**)&p_wz, g_wz);
    cudaGetSymbolAddress((void**)&p_h0, g_h0);
    cudaGetSymbolAddress((void**)&p_hT, g_hT);
    cudaGetSymbolAddress((void**)&p_fl, g_flags);

    int smem_scan = BB*HH*(int)sizeof(float) + 128*REDS*(int)sizeof(u64); // 132096
    cudaFuncSetAttribute(scan_kernel,
        cudaFuncAttributeMaxDynamicSharedMemorySize, smem_scan);

    init_kernel<<<128, 256>>>(x_len, out, out_size);

    dim3 gg(HH/128, (TT*BB)/64);   // (8, 375)

    // ---- layer 0 ----
    gemm_bn_kernel<<<gg, 256>>>(x, whW0, p_wh, bnh_g0, bnh_b0, bnh_m0, bnh_v0, DD);
    gemm_bn_kernel<<<gg, 256>>>(x, wzW0, p_wz, bnz_g0, bnz_b0, bnz_m0, bnz_v0, DD);
    scan_kernel<<<GRID_SCAN, 256, smem_scan>>>(p_wh, p_wz, uhW0, uzW0, p_h0,
                                               p_hT, p_hT + BB*HH, p_fl);

    // ---- layer 1 ----
    gemm_bn_kernel<<<gg, 256>>>(p_h0, whW1, p_wh, bnh_g1, bnh_b1, bnh_m1, bnh_v1, HH);
    gemm_bn_kernel<<<gg, 256>>>(p_h0, wzW1, p_wz, bnz_g1, bnz_b1, bnz_m1, bnz_v1, HH);
    scan_kernel<<<GRID_SCAN, 256, smem_scan>>>(p_wh, p_wz, uhW1, uzW1, out,
                                               p_hT + 2*BB*HH, p_hT + 3*BB*HH,
                                               p_fl + GRID_SCAN*FPAD);
}

// round 8
// speedup vs baseline: 1.2605x; 1.2605x over previous
#include <cuda_runtime.h>
#include <math.h>

#define TT 1500
#define BB 16
#define DD 512
#define HH 1024
#define KEEPF 0.8f
#define EPSF 1e-5f
#define NTOT (TT*BB*HH)
#define GRID_SCAN 128
#define REDS 65                     // padded red row stride (u64)
#define FPAD 32                     // ints per flag slot (128B)

typedef unsigned long long u64;

#define FMA2(d,a,b,c) asm("fma.rn.f32x2 %0, %1, %2, %3;" : "=l"(d) : "l"(a), "l"(b), "l"(c))
#define ADD2(d,a,b)   asm("add.rn.f32x2 %0, %1, %2;" : "=l"(d) : "l"(a), "l"(b))
#define PACK2(d,lo,hi) asm("mov.b64 %0, {%1, %2};" : "=l"(d) : "f"(lo), "f"(hi))
#define UNPACK2(lo,hi,in) asm("mov.b64 {%0, %1}, %2;" : "=f"(lo), "=f"(hi) : "l"(in))

// -------- scratch (device globals: no allocation allowed) --------
__device__ float g_wh[NTOT];
__device__ float g_wz[NTOT];
__device__ float g_h0[NTOT];
__device__ float g_hT[BB*HH];          // h_t broadcast buffer, [b][k]
__device__ int   g_flags[2*GRID_SCAN*FPAD];

// =================================================================
__global__ void init_kernel(const int* __restrict__ x_len,
                            float* __restrict__ out, int out_size)
{
    int i = blockIdx.x * blockDim.x + threadIdx.x;
    if (i < 2*GRID_SCAN*FPAD) g_flags[i] = 0;
    if (out_size >= NTOT + BB && i < BB) out[NTOT + i] = (float)x_len[i];
}

// =================================================================
// GEMM v2 + fused eval BatchNorm.
// C[m][n] = bn( sum_k A[m][k]*W[n][k] )
// BM=64, BN=256, BK=8; 256 threads; 8x8 microtile per thread.
// A smem UNduplicated; broadcast operand packed in registers
// (mov.b64 on ALU pipe) so crossbar and FMA2 pipes balance at
// ~1024 cyc/tile for 131072 MACs (128 MAC/cyc/SM).
// Double-buffered smem, one __syncthreads per k-tile.
// =================================================================
__global__ void __launch_bounds__(256) gemm_bn_kernel(
    const float* __restrict__ A, const float* __restrict__ W,
    float* __restrict__ C,
    const float* __restrict__ gam, const float* __restrict__ bet,
    const float* __restrict__ mu,  const float* __restrict__ var,
    int K)
{
    __shared__ float As[2][8][68];    // [buf][k][m]
    __shared__ float Bs[2][8][264];   // [buf][k][n]

    int tid = threadIdx.x;
    int m0 = blockIdx.y * 64;
    int n0 = blockIdx.x * 256;

    int tx = tid & 31;               // n-tile: 8 cols each
    int ty = tid >> 5;               // m-tile: 8 rows each

    // A loaders: threads 0..127, one float4 each (64 rows x 8 k)
    int arow = tid >> 1;             // 0..127 -> but only <64 rows used by tid<128
    int acol = (tid & 1) * 4;
    bool a_ld = (tid < 128);
    const float* Ap = A + (size_t)(m0 + (arow & 63)) * K + acol;
    // B loaders: all 256 threads, one W row (8 k) each
    const float* Wp = W + (size_t)(n0 + tid) * K;

    float4 ar = a_ld ? *(const float4*)Ap : make_float4(0.f,0.f,0.f,0.f);
    float4 br0 = *(const float4*)Wp;
    float4 br1 = *(const float4*)(Wp + 4);

    u64 acc[8][4];
    #pragma unroll
    for (int i = 0; i < 8; i++)
        #pragma unroll
        for (int j = 0; j < 4; j++) acc[i][j] = 0ull;

    int nk = K >> 3;
    int am = ty * 8;
    int bn = tx * 8;

    for (int kt = 0; kt < nk; kt++) {
        int p = kt & 1;
        if (a_ld) {
            As[p][acol  ][arow] = ar.x;
            As[p][acol+1][arow] = ar.y;
            As[p][acol+2][arow] = ar.z;
            As[p][acol+3][arow] = ar.w;
        }
        Bs[p][0][tid] = br0.x;
        Bs[p][1][tid] = br0.y;
        Bs[p][2][tid] = br0.z;
        Bs[p][3][tid] = br0.w;
        Bs[p][4][tid] = br1.x;
        Bs[p][5][tid] = br1.y;
        Bs[p][6][tid] = br1.z;
        Bs[p][7][tid] = br1.w;
        if (kt + 1 < nk) {
            int ko = (kt + 1) * 8;
            if (a_ld) ar = *(const float4*)(Ap + ko);
            br0 = *(const float4*)(Wp + ko);
            br1 = *(const float4*)(Wp + ko + 4);
        }
        __syncthreads();
        #pragma unroll
        for (int kk = 0; kk < 8; kk++) {
            float4 a0 = *(const float4*)&As[p][kk][am];
            float4 a1 = *(const float4*)&As[p][kk][am+4];
            ulonglong2 b0 = *(const ulonglong2*)&Bs[p][kk][bn];
            ulonglong2 b1 = *(const ulonglong2*)&Bs[p][kk][bn+4];
            u64 bv[4] = {b0.x, b0.y, b1.x, b1.y};
            u64 ad[8];
            PACK2(ad[0], a0.x, a0.x);
            PACK2(ad[1], a0.y, a0.y);
            PACK2(ad[2], a0.z, a0.z);
            PACK2(ad[3], a0.w, a0.w);
            PACK2(ad[4], a1.x, a1.x);
            PACK2(ad[5], a1.y, a1.y);
            PACK2(ad[6], a1.z, a1.z);
            PACK2(ad[7], a1.w, a1.w);
            #pragma unroll
            for (int i = 0; i < 8; i++)
                #pragma unroll
                for (int j = 0; j < 4; j++)
                    FMA2(acc[i][j], ad[i], bv[j], acc[i][j]);
        }
        __syncthreads();
    }

    // fused BN epilogue: y = x*sc + sh, pair-packed over n
    float sc[8], sh[8];
    #pragma unroll
    for (int j = 0; j < 8; j++) {
        int n = n0 + bn + j;
        float inv = rsqrtf(var[n] + EPSF);
        sc[j] = gam[n] * inv;
        sh[j] = bet[n] - mu[n] * sc[j];
    }
    u64 sc2[4], sh2[4];
    #pragma unroll
    for (int j = 0; j < 4; j++) {
        PACK2(sc2[j], sc[2*j], sc[2*j+1]);
        PACK2(sh2[j], sh[2*j], sh[2*j+1]);
    }
    #pragma unroll
    for (int i = 0; i < 8; i++) {
        size_t row = (size_t)(m0 + am + i) * HH + n0 + bn;
        u64 o[4];
        #pragma unroll
        for (int j = 0; j < 4; j++) FMA2(o[j], acc[i][j], sc2[j], sh2[j]);
        ulonglong2 s0; s0.x = o[0]; s0.y = o[1];
        ulonglong2 s1; s1.x = o[2]; s1.y = o[3];
        *(ulonglong2*)(C + row)     = s0;
        *(ulonglong2*)(C + row + 4) = s1;
    }
}

// =================================================================
// persistent liGRU scan (R5 version, known-good 6.63ms/layer).
// =================================================================
__global__ void __launch_bounds__(256, 1) scan_kernel(
    const float* __restrict__ WH, const float* __restrict__ WZ,
    const float* __restrict__ Uh, const float* __restrict__ Uz,
    float* __restrict__ Hout, float* __restrict__ hT,
    int* __restrict__ flags)
{
    extern __shared__ float smem[];
    float* hs  = smem;                       // [16][1024]
    u64*   red = (u64*)(smem + BB*HH);       // [128][REDS]

    int tid = threadIdx.x;
    int qd  = tid >> 7;            // 0..1 quad
    int bh  = (tid >> 6) & 1;      // 0..1 batch-half
    int kg  = tid & 63;            // 0..63 k-slice
    int j0  = blockIdx.x * 8;

    // ---- stationary U in registers: pair-packed ----
    u64 uz[2][16], uh[2][16];
    #pragma unroll
    for (int pr = 0; pr < 2; pr++) {
        const float* z0 = Uz + (size_t)(j0 + qd*4 + 2*pr)*HH;
        const float* z1 = z0 + HH;
        const float* a0 = Uh + (size_t)(j0 + qd*4 + 2*pr)*HH;
        const float* a1 = a0 + HH;
        #pragma unroll
        for (int kk = 0; kk < 16; kk++) {
            int k = kg + (kk << 6);
            PACK2(uz[pr][kk], z0[k], z1[k]);
            PACK2(uh[pr][kk], a0[k], a1[k]);
        }
    }
    for (int idx = tid; idx < BB*HH; idx += 256) hs[idx] = 0.f;   // h0 = 0
    __syncthreads();

    int r_b   = tid & 15;
    int r_grp = tid >> 4;
    int r_m   = r_grp & 1;
    int g_qd  = (r_grp >> 2) & 1;
    int g_pr  = (r_grp >> 1) & 1;
    int jg    = j0 + g_qd*4 + g_pr*2;
    bool is_red  = (tid < 128);
    bool is_gate = is_red && (r_m == 0);

    for (int t = 0; t < TT; t++) {
        float2 wz2 = make_float2(0.f, 0.f), wh2 = wz2;
        size_t ob = 0;
        if (is_gate) {
            ob = ((size_t)t*BB + r_b)*HH + jg;
            wz2 = *(const float2*)(WZ + ob);
            wh2 = *(const float2*)(WH + ob);
        }

        u64 az[2][8], ah[2][8];
        #pragma unroll
        for (int pr = 0; pr < 2; pr++)
            #pragma unroll
            for (int b = 0; b < 8; b++) { az[pr][b] = 0ull; ah[pr][b] = 0ull; }

        {
            const float* hb = hs + (bh << 3)*HH + kg;
            #pragma unroll
            for (int kk = 0; kk < 16; kk++) {
                const float* hk = hb + (kk << 6);
                #pragma unroll
                for (int b = 0; b < 8; b++) {
                    float hv = hk[b*HH];
                    u64 hd; PACK2(hd, hv, hv);
                    FMA2(az[0][b], hd, uz[0][kk], az[0][b]);
                    FMA2(ah[0][b], hd, uh[0][kk], ah[0][b]);
                    FMA2(az[1][b], hd, uz[1][kk], az[1][b]);
                    FMA2(ah[1][b], hd, uh[1][kk], ah[1][b]);
                }
            }
        }

        {
            u64* rp = red + kg;
            #pragma unroll
            for (int pr = 0; pr < 2; pr++)
                #pragma unroll
                for (int b = 0; b < 8; b++) {
                    int bb = (bh << 3) + b;
                    rp[((qd*4 + pr*2    )*16 + bb)*REDS] = az[pr][b];
                    rp[((qd*4 + pr*2 + 1)*16 + bb)*REDS] = ah[pr][b];
                }
        }
        __syncthreads();

        if (is_red) {
            const u64* rr = red + (size_t)tid*REDS;
            u64 s0 = 0ull, s1 = 0ull, s2 = 0ull, s3 = 0ull;
            #pragma unroll
            for (int i = 0; i < 64; i += 4) {
                ADD2(s0, s0, rr[i]);
                ADD2(s1, s1, rr[i+1]);
                ADD2(s2, s2, rr[i+2]);
                ADD2(s3, s3, rr[i+3]);
            }
            ADD2(s0, s0, s1);
            ADD2(s2, s2, s3);
            ADD2(s0, s0, s2);
            u64 part = __shfl_xor_sync(0xffffffffu, s0, 16);
            if (is_gate) {
                float z0, z1, a0, a1;
                UNPACK2(z0, z1, s0);
                UNPACK2(a0, a1, part);
                float zt0 = 1.f / (1.f + __expf(-(wz2.x + z0)));
                float zt1 = 1.f / (1.f + __expf(-(wz2.y + z1)));
                float hc0 = fmaxf(wh2.x + a0, 0.f) * KEEPF;
                float hc1 = fmaxf(wh2.y + a1, 0.f) * KEEPF;
                float2 ho = *(const float2*)(hs + r_b*HH + jg);
                float2 hn;
                hn.x = zt0*ho.x + (1.f - zt0)*hc0;
                hn.y = zt1*ho.y + (1.f - zt1)*hc1;
                *(float2*)(Hout + ob)        = hn;
                *(float2*)(hT + r_b*HH + jg) = hn;
            }
        }
        __syncthreads();
        if (t == TT-1) break;

        if (tid == 0) {
            asm volatile("st.release.gpu.global.s32 [%0], %1;"
                         :: "l"(flags + blockIdx.x*FPAD), "r"(t+1) : "memory");
        }
        if (tid < GRID_SCAN) {
            const int* fp = flags + tid*FPAD;
            int v;
            do {
                asm volatile("ld.acquire.gpu.global.s32 %0, [%1];"
                             : "=r"(v) : "l"(fp) : "memory");
            } while (v <= t);
        }
        __syncthreads();

        {
            const float4* src = (const float4*)hT;
            float4* dst = (float4*)hs;
            #pragma unroll
            for (int i = 0; i < 16; i++)
                dst[tid + (i << 8)] = __ldcg(src + tid + (i << 8));
        }
        __syncthreads();
    }
}

// =================================================================
extern "C" void kernel_launch(void* const* d_in, const int* in_sizes, int n_in,
                              void* d_out, int out_size)
{
    const float* x     = (const float*)d_in[0];
    const int*   x_len = (const int*)  d_in[1];
    const float* whW0  = (const float*)d_in[2];
    const float* wzW0  = (const float*)d_in[3];
    const float* uhW0  = (const float*)d_in[4];
    const float* uzW0  = (const float*)d_in[5];
    const float* bnh_g0 = (const float*)d_in[6];
    const float* bnh_b0 = (const float*)d_in[7];
    const float* bnh_m0 = (const float*)d_in[8];
    const float* bnh_v0 = (const float*)d_in[9];
    const float* bnz_g0 = (const float*)d_in[10];
    const float* bnz_b0 = (const float*)d_in[11];
    const float* bnz_m0 = (const float*)d_in[12];
    const float* bnz_v0 = (const float*)d_in[13];
    const float* whW1  = (const float*)d_in[14];
    const float* wzW1  = (const float*)d_in[15];
    const float* uhW1  = (const float*)d_in[16];
    const float* uzW1  = (const float*)d_in[17];
    const float* bnh_g1 = (const float*)d_in[18];
    const float* bnh_b1 = (const float*)d_in[19];
    const float* bnh_m1 = (const float*)d_in[20];
    const float* bnh_v1 = (const float*)d_in[21];
    const float* bnz_g1 = (const float*)d_in[22];
    const float* bnz_b1 = (const float*)d_in[23];
    const float* bnz_m1 = (const float*)d_in[24];
    const float* bnz_v1 = (const float*)d_in[25];

    float* out = (float*)d_out;

    float *p_wh, *p_wz, *p_h0, *p_hT; int* p_fl;
    cudaGetSymbolAddress((void**)&p_wh, g_wh);
    cudaGetSymbolAddress((void**)&p_wz, g_wz);
    cudaGetSymbolAddress((void**)&p_h0, g_h0);
    cudaGetSymbolAddress((void**)&p_hT, g_hT);
    cudaGetSymbolAddress((void**)&p_fl, g_flags);

    int smem_scan = BB*HH*(int)sizeof(float) + 128*REDS*(int)sizeof(u64); // 132096
    cudaFuncSetAttribute(scan_kernel,
        cudaFuncAttributeMaxDynamicSharedMemorySize, smem_scan);

    init_kernel<<<32, 256>>>(x_len, out, out_size);

    dim3 gg(HH/256, (TT*BB)/64);   // (4, 375)

    // ---- layer 0 ----
    gemm_bn_kernel<<<gg, 256>>>(x, whW0, p_wh, bnh_g0, bnh_b0, bnh_m0, bnh_v0, DD);
    gemm_bn_kernel<<<gg, 256>>>(x, wzW0, p_wz, bnz_g0, bnz_b0, bnz_m0, bnz_v0, DD);
    scan_kernel<<<GRID_SCAN, 256, smem_scan>>>(p_wh, p_wz, uhW0, uzW0, p_h0, p_hT, p_fl);

    // ---- layer 1 ----
    gemm_bn_kernel<<<gg, 256>>>(p_h0, whW1, p_wh, bnh_g1, bnh_b1, bnh_m1, bnh_v1, HH);
    gemm_bn_kernel<<<gg, 256>>>(p_h0, wzW1, p_wz, bnz_g1, bnz_b1, bnz_m1, bnz_v1, HH);
    scan_kernel<<<GRID_SCAN, 256, smem_scan>>>(p_wh, p_wz, uhW1, uzW1, out, p_hT,
                                               p_fl + GRID_SCAN*FPAD);
}

// round 9
// speedup vs baseline: 1.3432x; 1.0656x over previous
#include <cuda_runtime.h>
#include <math.h>

#define TT 1500
#define BB 16
#define DD 512
#define HH 1024
#define KEEPF 0.8f
#define EPSF 1e-5f
#define NTOT (TT*BB*HH)
#define GRID_SCAN 128
#define REDS 65                     // padded red row stride (u64)
#define FPAD 32                     // ints per flag slot (128B)

typedef unsigned long long u64;

#define FMA2(d,a,b,c) asm("fma.rn.f32x2 %0, %1, %2, %3;" : "=l"(d) : "l"(a), "l"(b), "l"(c))
#define ADD2(d,a,b)   asm("add.rn.f32x2 %0, %1, %2;" : "=l"(d) : "l"(a), "l"(b))
#define PACK2(d,lo,hi) asm("mov.b64 %0, {%1, %2};" : "=l"(d) : "f"(lo), "f"(hi))
#define UNPACK2(lo,hi,in) asm("mov.b64 {%0, %1}, %2;" : "=f"(lo), "=f"(hi) : "l"(in))
#define CPA_COMMIT() asm volatile("cp.async.commit_group;" ::: "memory")
#define CPA_WAIT(n)  asm volatile("cp.async.wait_group %0;" :: "n"(n) : "memory")

// -------- scratch (device globals: no allocation allowed) --------
__device__ float g_wh[NTOT];
__device__ float g_wz[NTOT];
__device__ float g_h0[NTOT];
__device__ float g_hT[BB*HH];          // h_t broadcast buffer, [b][k]
__device__ int   g_flags[2*GRID_SCAN*FPAD];

// =================================================================
__global__ void init_kernel(const int* __restrict__ x_len,
                            float* __restrict__ out, int out_size)
{
    int i = blockIdx.x * blockDim.x + threadIdx.x;
    if (i < 2*GRID_SCAN*FPAD) g_flags[i] = 0;
    if (out_size >= NTOT + BB && i < BB) out[NTOT + i] = (float)x_len[i];
}

// =================================================================
// GEMM v2 + fused eval BatchNorm (R8 tile, now 2 CTAs/SM).
// BM=64, BN=256, BK=8; 256 threads; 8x8 microtile per thread.
// =================================================================
__global__ void __launch_bounds__(256, 2) gemm_bn_kernel(
    const float* __restrict__ A, const float* __restrict__ W,
    float* __restrict__ C,
    const float* __restrict__ gam, const float* __restrict__ bet,
    const float* __restrict__ mu,  const float* __restrict__ var,
    int K)
{
    __shared__ float As[2][8][68];    // [buf][k][m]
    __shared__ float Bs[2][8][264];   // [buf][k][n]

    int tid = threadIdx.x;
    int m0 = blockIdx.y * 64;
    int n0 = blockIdx.x * 256;

    int tx = tid & 31;               // n-tile: 8 cols each
    int ty = tid >> 5;               // m-tile: 8 rows each

    int arow = tid >> 1;
    int acol = (tid & 1) * 4;
    bool a_ld = (tid < 128);
    const float* Ap = A + (size_t)(m0 + (arow & 63)) * K + acol;
    const float* Wp = W + (size_t)(n0 + tid) * K;

    float4 ar = a_ld ? *(const float4*)Ap : make_float4(0.f,0.f,0.f,0.f);
    float4 br0 = *(const float4*)Wp;
    float4 br1 = *(const float4*)(Wp + 4);

    u64 acc[8][4];
    #pragma unroll
    for (int i = 0; i < 8; i++)
        #pragma unroll
        for (int j = 0; j < 4; j++) acc[i][j] = 0ull;

    int nk = K >> 3;
    int am = ty * 8;
    int bn = tx * 8;

    for (int kt = 0; kt < nk; kt++) {
        int p = kt & 1;
        if (a_ld) {
            As[p][acol  ][arow] = ar.x;
            As[p][acol+1][arow] = ar.y;
            As[p][acol+2][arow] = ar.z;
            As[p][acol+3][arow] = ar.w;
        }
        Bs[p][0][tid] = br0.x;
        Bs[p][1][tid] = br0.y;
        Bs[p][2][tid] = br0.z;
        Bs[p][3][tid] = br0.w;
        Bs[p][4][tid] = br1.x;
        Bs[p][5][tid] = br1.y;
        Bs[p][6][tid] = br1.z;
        Bs[p][7][tid] = br1.w;
        if (kt + 1 < nk) {
            int ko = (kt + 1) * 8;
            if (a_ld) ar = *(const float4*)(Ap + ko);
            br0 = *(const float4*)(Wp + ko);
            br1 = *(const float4*)(Wp + ko + 4);
        }
        __syncthreads();
        #pragma unroll
        for (int kk = 0; kk < 8; kk++) {
            float4 a0 = *(const float4*)&As[p][kk][am];
            float4 a1 = *(const float4*)&As[p][kk][am+4];
            ulonglong2 b0 = *(const ulonglong2*)&Bs[p][kk][bn];
            ulonglong2 b1 = *(const ulonglong2*)&Bs[p][kk][bn+4];
            u64 bv[4] = {b0.x, b0.y, b1.x, b1.y};
            u64 ad[8];
            PACK2(ad[0], a0.x, a0.x);
            PACK2(ad[1], a0.y, a0.y);
            PACK2(ad[2], a0.z, a0.z);
            PACK2(ad[3], a0.w, a0.w);
            PACK2(ad[4], a1.x, a1.x);
            PACK2(ad[5], a1.y, a1.y);
            PACK2(ad[6], a1.z, a1.z);
            PACK2(ad[7], a1.w, a1.w);
            #pragma unroll
            for (int i = 0; i < 8; i++)
                #pragma unroll
                for (int j = 0; j < 4; j++)
                    FMA2(acc[i][j], ad[i], bv[j], acc[i][j]);
        }
        __syncthreads();
    }

    float sc[8], sh[8];
    #pragma unroll
    for (int j = 0; j < 8; j++) {
        int n = n0 + bn + j;
        float inv = rsqrtf(var[n] + EPSF);
        sc[j] = gam[n] * inv;
        sh[j] = bet[n] - mu[n] * sc[j];
    }
    u64 sc2[4], sh2[4];
    #pragma unroll
    for (int j = 0; j < 4; j++) {
        PACK2(sc2[j], sc[2*j], sc[2*j+1]);
        PACK2(sh2[j], sh[2*j], sh[2*j+1]);
    }
    #pragma unroll
    for (int i = 0; i < 8; i++) {
        size_t row = (size_t)(m0 + am + i) * HH + n0 + bn;
        u64 o[4];
        #pragma unroll
        for (int j = 0; j < 4; j++) FMA2(o[j], acc[i][j], sc2[j], sh2[j]);
        ulonglong2 s0; s0.x = o[0]; s0.y = o[1];
        ulonglong2 s1; s1.x = o[2]; s1.y = o[3];
        *(ulonglong2*)(C + row)     = s0;
        *(ulonglong2*)(C + row + 4) = s1;
    }
}

// =================================================================
// persistent liGRU scan v6 = R5 + pipelined cp.async h-reload.
// Tail (after barrier): issue chunk0 (k<512) and chunk1 (k>=512)
// as two cp.async.cg commit groups.  Head: wait c0 -> compute
// kk 0-7 (c1 in flight) -> wait c1 -> compute kk 8-15.
// =================================================================
__global__ void __launch_bounds__(256, 1) scan_kernel(
    const float* __restrict__ WH, const float* __restrict__ WZ,
    const float* __restrict__ Uh, const float* __restrict__ Uz,
    float* __restrict__ Hout, float* __restrict__ hT,
    int* __restrict__ flags)
{
    extern __shared__ float smem[];
    float* hs  = smem;                       // [16][1024]
    u64*   red = (u64*)(smem + BB*HH);       // [128][REDS]

    int tid = threadIdx.x;
    int qd  = tid >> 7;            // 0..1 quad
    int bh  = (tid >> 6) & 1;      // 0..1 batch-half
    int kg  = tid & 63;            // 0..63 k-slice
    int j0  = blockIdx.x * 8;

    // ---- stationary U in registers: pair-packed ----
    u64 uz[2][16], uh[2][16];
    #pragma unroll
    for (int pr = 0; pr < 2; pr++) {
        const float* z0 = Uz + (size_t)(j0 + qd*4 + 2*pr)*HH;
        const float* z1 = z0 + HH;
        const float* a0 = Uh + (size_t)(j0 + qd*4 + 2*pr)*HH;
        const float* a1 = a0 + HH;
        #pragma unroll
        for (int kk = 0; kk < 16; kk++) {
            int k = kg + (kk << 6);
            PACK2(uz[pr][kk], z0[k], z1[k]);
            PACK2(uh[pr][kk], a0[k], a1[k]);
        }
    }
    for (int idx = tid; idx < BB*HH; idx += 256) hs[idx] = 0.f;   // h0 = 0
    __syncthreads();

    int r_b   = tid & 15;
    int r_grp = tid >> 4;
    int r_m   = r_grp & 1;
    int g_qd  = (r_grp >> 2) & 1;
    int g_pr  = (r_grp >> 1) & 1;
    int jg    = j0 + g_qd*4 + g_pr*2;
    bool is_red  = (tid < 128);
    bool is_gate = is_red && (r_m == 0);

    for (int t = 0; t < TT; t++) {
        // prefetch pre-projections (LDGs fly over the cp.async wait)
        float2 wz2 = make_float2(0.f, 0.f), wh2 = wz2;
        size_t ob = 0;
        if (is_gate) {
            ob = ((size_t)t*BB + r_b)*HH + jg;
            wz2 = *(const float2*)(WZ + ob);
            wh2 = *(const float2*)(WH + ob);
        }

        u64 az[2][8], ah[2][8];
        #pragma unroll
        for (int pr = 0; pr < 2; pr++)
            #pragma unroll
            for (int b = 0; b < 8; b++) { az[pr][b] = 0ull; ah[pr][b] = 0ull; }

        const float* hb = hs + (bh << 3)*HH + kg;

        // ---- chunk0 ready (k<512): compute kk 0-7 while chunk1 flies ----
        CPA_WAIT(1);
        __syncthreads();
        #pragma unroll
        for (int kk = 0; kk < 8; kk++) {
            const float* hk = hb + (kk << 6);
            #pragma unroll
            for (int b = 0; b < 8; b++) {
                float hv = hk[b*HH];
                u64 hd; PACK2(hd, hv, hv);
                FMA2(az[0][b], hd, uz[0][kk], az[0][b]);
                FMA2(ah[0][b], hd, uh[0][kk], ah[0][b]);
                FMA2(az[1][b], hd, uz[1][kk], az[1][b]);
                FMA2(ah[1][b], hd, uh[1][kk], ah[1][b]);
            }
        }
        // ---- chunk1 ready (k>=512): compute kk 8-15 ----
        CPA_WAIT(0);
        __syncthreads();
        #pragma unroll
        for (int kk = 8; kk < 16; kk++) {
            const float* hk = hb + (kk << 6);
            #pragma unroll
            for (int b = 0; b < 8; b++) {
                float hv = hk[b*HH];
                u64 hd; PACK2(hd, hv, hv);
                FMA2(az[0][b], hd, uz[0][kk], az[0][b]);
                FMA2(ah[0][b], hd, uh[0][kk], ah[0][b]);
                FMA2(az[1][b], hd, uz[1][kk], az[1][b]);
                FMA2(ah[1][b], hd, uh[1][kk], ah[1][b]);
            }
        }

        // ---- k-partial write: red[grp*16 + b][kg] ----
        {
            u64* rp = red + kg;
            #pragma unroll
            for (int pr = 0; pr < 2; pr++)
                #pragma unroll
                for (int b = 0; b < 8; b++) {
                    int bb = (bh << 3) + b;
                    rp[((qd*4 + pr*2    )*16 + bb)*REDS] = az[pr][b];
                    rp[((qd*4 + pr*2 + 1)*16 + bb)*REDS] = ah[pr][b];
                }
        }
        __syncthreads();

        // ---- 4-warp reduce + partner exchange + gate ----
        if (is_red) {
            const u64* rr = red + (size_t)tid*REDS;
            u64 s0 = 0ull, s1 = 0ull, s2 = 0ull, s3 = 0ull;
            #pragma unroll
            for (int i = 0; i < 64; i += 4) {
                ADD2(s0, s0, rr[i]);
                ADD2(s1, s1, rr[i+1]);
                ADD2(s2, s2, rr[i+2]);
                ADD2(s3, s3, rr[i+3]);
            }
            ADD2(s0, s0, s1);
            ADD2(s2, s2, s3);
            ADD2(s0, s0, s2);
            u64 part = __shfl_xor_sync(0xffffffffu, s0, 16);
            if (is_gate) {
                float z0, z1, a0, a1;
                UNPACK2(z0, z1, s0);
                UNPACK2(a0, a1, part);
                float zt0 = 1.f / (1.f + __expf(-(wz2.x + z0)));
                float zt1 = 1.f / (1.f + __expf(-(wz2.y + z1)));
                float hc0 = fmaxf(wh2.x + a0, 0.f) * KEEPF;
                float hc1 = fmaxf(wh2.y + a1, 0.f) * KEEPF;
                float2 ho = *(const float2*)(hs + r_b*HH + jg);
                float2 hn;
                hn.x = zt0*ho.x + (1.f - zt0)*hc0;
                hn.y = zt1*ho.y + (1.f - zt1)*hc1;
                *(float2*)(Hout + ob)        = hn;
                *(float2*)(hT + r_b*HH + jg) = hn;
            }
        }
        __syncthreads();
        if (t == TT-1) break;

        // ---- release/acquire distributed-flag grid barrier ----
        if (tid == 0) {
            asm volatile("st.release.gpu.global.s32 [%0], %1;"
                         :: "l"(flags + blockIdx.x*FPAD), "r"(t+1) : "memory");
        }
        if (tid < GRID_SCAN) {
            const int* fp = flags + tid*FPAD;
            int v;
            do {
                asm volatile("ld.acquire.gpu.global.s32 %0, [%1];"
                             : "=r"(v) : "l"(fp) : "memory");
            } while (v <= t);
        }
        __syncthreads();

        // ---- issue pipelined reload: hT -> hs, two 32KB chunks ----
        {
            // chunk0: float4 columns 0..127 of each batch row
            #pragma unroll
            for (int i = 0; i < 8; i++) {
                int idx = i*256 + tid;             // 0..2047
                int b = idx >> 7, c = idx & 127;
                const float* src = hT + b*HH + (c << 2);
                unsigned dst = (unsigned)__cvta_generic_to_shared(hs + b*HH + (c << 2));
                asm volatile("cp.async.cg.shared.global [%0], [%1], 16;"
                             :: "r"(dst), "l"(src) : "memory");
            }
            CPA_COMMIT();
            // chunk1: float4 columns 128..255
            #pragma unroll
            for (int i = 0; i < 8; i++) {
                int idx = i*256 + tid;
                int b = idx >> 7, c = (idx & 127) + 128;
                const float* src = hT + b*HH + (c << 2);
                unsigned dst = (unsigned)__cvta_generic_to_shared(hs + b*HH + (c << 2));
                asm volatile("cp.async.cg.shared.global [%0], [%1], 16;"
                             :: "r"(dst), "l"(src) : "memory");
            }
            CPA_COMMIT();
        }
    }
}

// =================================================================
extern "C" void kernel_launch(void* const* d_in, const int* in_sizes, int n_in,
                              void* d_out, int out_size)
{
    const float* x     = (const float*)d_in[0];
    const int*   x_len = (const int*)  d_in[1];
    const float* whW0  = (const float*)d_in[2];
    const float* wzW0  = (const float*)d_in[3];
    const float* uhW0  = (const float*)d_in[4];
    const float* uzW0  = (const float*)d_in[5];
    const float* bnh_g0 = (const float*)d_in[6];
    const float* bnh_b0 = (const float*)d_in[7];
    const float* bnh_m0 = (const float*)d_in[8];
    const float* bnh_v0 = (const float*)d_in[9];
    const float* bnz_g0 = (const float*)d_in[10];
    const float* bnz_b0 = (const float*)d_in[11];
    const float* bnz_m0 = (const float*)d_in[12];
    const float* bnz_v0 = (const float*)d_in[13];
    const float* whW1  = (const float*)d_in[14];
    const float* wzW1  = (const float*)d_in[15];
    const float* uhW1  = (const float*)d_in[16];
    const float* uzW1  = (const float*)d_in[17];
    const float* bnh_g1 = (const float*)d_in[18];
    const float* bnh_b1 = (const float*)d_in[19];
    const float* bnh_m1 = (const float*)d_in[20];
    const float* bnh_v1 = (const float*)d_in[21];
    const float* bnz_g1 = (const float*)d_in[22];
    const float* bnz_b1 = (const float*)d_in[23];
    const float* bnz_m1 = (const float*)d_in[24];
    const float* bnz_v1 = (const float*)d_in[25];

    float* out = (float*)d_out;

    float *p_wh, *p_wz, *p_h0, *p_hT; int* p_fl;
    cudaGetSymbolAddress((void**)&p_wh, g_wh);
    cudaGetSymbolAddress((void**)&p_wz, g_wz);
    cudaGetSymbolAddress((void**)&p_h0, g_h0);
    cudaGetSymbolAddress((void**)&p_hT, g_hT);
    cudaGetSymbolAddress((void**)&p_fl, g_flags);

    int smem_scan = BB*HH*(int)sizeof(float) + 128*REDS*(int)sizeof(u64); // 132096
    cudaFuncSetAttribute(scan_kernel,
        cudaFuncAttributeMaxDynamicSharedMemorySize, smem_scan);

    init_kernel<<<32, 256>>>(x_len, out, out_size);

    dim3 gg(HH/256, (TT*BB)/64);   // (4, 375)

    // ---- layer 0 ----
    gemm_bn_kernel<<<gg, 256>>>(x, whW0, p_wh, bnh_g0, bnh_b0, bnh_m0, bnh_v0, DD);
    gemm_bn_kernel<<<gg, 256>>>(x, wzW0, p_wz, bnz_g0, bnz_b0, bnz_m0, bnz_v0, DD);
    scan_kernel<<<GRID_SCAN, 256, smem_scan>>>(p_wh, p_wz, uhW0, uzW0, p_h0, p_hT, p_fl);

    // ---- layer 1 ----
    gemm_bn_kernel<<<gg, 256>>>(p_h0, whW1, p_wh, bnh_g1, bnh_b1, bnh_m1, bnh_v1, HH);
    gemm_bn_kernel<<<gg, 256>>>(p_h0, wzW1, p_wz, bnz_g1, bnz_b1, bnz_m1, bnz_v1, HH);
    scan_kernel<<<GRID_SCAN, 256, smem_scan>>>(p_wh, p_wz, uhW1, uzW1, out, p_hT,
                                               p_fl + GRID_SCAN*FPAD);
}

// round 12
// speedup vs baseline: 1.5429x; 1.1487x over previous
#include <cuda_runtime.h>
#include <cuda_bf16.h>
#include <cstdint>
#include <math.h>

#define TT 1500
#define BB 16
#define DD 512
#define HH 1024
#define KEEPF 0.8f
#define EPSF 1e-5f
#define NTOT (TT*BB*HH)
#define GRID_SCAN 128
#define REDS 65
#define FPAD 32
#define MTOT (TT*BB)                 // 24000 rows
#define MTILES ((MTOT + 127)/128)    // 188

typedef unsigned long long u64;

#define FMA2(d,a,b,c) asm("fma.rn.f32x2 %0, %1, %2, %3;" : "=l"(d) : "l"(a), "l"(b), "l"(c))
#define ADD2(d,a,b)   asm("add.rn.f32x2 %0, %1, %2;" : "=l"(d) : "l"(a), "l"(b))
#define PACK2(d,lo,hi) asm("mov.b64 %0, {%1, %2};" : "=l"(d) : "f"(lo), "f"(hi))
#define UNPACK2(lo,hi,in) asm("mov.b64 {%0, %1}, %2;" : "=f"(lo), "=f"(hi) : "l"(in))
#define CPA_COMMIT() asm volatile("cp.async.commit_group;" ::: "memory")
#define CPA_WAIT(n)  asm volatile("cp.async.wait_group %0;" :: "n"(n) : "memory")

#define SMEM_SWZ(o) ((o) ^ (((o) >> 3) & 0x70))

__device__ __forceinline__ uint32_t smem_u32(const void* p) {
    uint32_t a;
    asm("{ .reg .u64 t; cvta.to.shared.u64 t, %1; cvt.u32.u64 %0, t; }" : "=r"(a) : "l"(p));
    return a;
}

// warp-level bf16 tensor op (baseline ISA — works on compute_103 target)
#define LDSM_X4(r0,r1,r2,r3,addr) \
    asm volatile("ldmatrix.sync.aligned.m8n8.x4.shared.b16 {%0,%1,%2,%3}, [%4];" \
        : "=r"(r0), "=r"(r1), "=r"(r2), "=r"(r3) : "r"(addr))
#define LDSM_X2(r0,r1,addr) \
    asm volatile("ldmatrix.sync.aligned.m8n8.x2.shared.b16 {%0,%1}, [%2];" \
        : "=r"(r0), "=r"(r1) : "r"(addr))
#define MMA16816(d,a,b) \
    asm volatile("mma.sync.aligned.m16n8k16.row.col.f32.bf16.bf16.f32 " \
        "{%0,%1,%2,%3}, {%4,%5,%6,%7}, {%8,%9}, {%0,%1,%2,%3};" \
        : "+f"((d)[0]), "+f"((d)[1]), "+f"((d)[2]), "+f"((d)[3]) \
        : "r"((a)[0]), "r"((a)[1]), "r"((a)[2]), "r"((a)[3]), \
          "r"((b)[0]), "r"((b)[1]))

// -------- scratch (device globals: no allocation allowed) --------
__device__ float g_wh[NTOT];
__device__ float g_wz[NTOT];
__device__ float g_h0[NTOT];
__device__ float g_hT[BB*HH];
__device__ int   g_flags[2*GRID_SCAN*FPAD];
__device__ __nv_bfloat16 g_ahi[MTOT*HH];
__device__ __nv_bfloat16 g_alo[MTOT*HH];
__device__ __nv_bfloat16 g_whi[HH*HH];
__device__ __nv_bfloat16 g_wlo[HH*HH];

// =================================================================
__global__ void init_kernel(const int* __restrict__ x_len,
                            float* __restrict__ out, int out_size)
{
    int i = blockIdx.x * blockDim.x + threadIdx.x;
    if (i < 2*GRID_SCAN*FPAD) g_flags[i] = 0;
    if (out_size >= NTOT + BB && i < BB) out[NTOT + i] = (float)x_len[i];
}

// =================================================================
// fp32 -> (bf16 hi, bf16 lo) split, vectorized
// =================================================================
__global__ void split_kernel(const float* __restrict__ src,
                             __nv_bfloat16* __restrict__ hi,
                             __nv_bfloat16* __restrict__ lo, int n)
{
    int i = (blockIdx.x * blockDim.x + threadIdx.x) * 4;
    int stride = gridDim.x * blockDim.x * 4;
    for (; i < n; i += stride) {
        float4 x = *(const float4*)(src + i);
        __nv_bfloat16 h0 = __float2bfloat16(x.x), h1 = __float2bfloat16(x.y);
        __nv_bfloat16 h2 = __float2bfloat16(x.z), h3 = __float2bfloat16(x.w);
        __nv_bfloat162 H0; H0.x = h0; H0.y = h1;
        __nv_bfloat162 H1; H1.x = h2; H1.y = h3;
        *(__nv_bfloat162*)(hi + i)     = H0;
        *(__nv_bfloat162*)(hi + i + 2) = H1;
        __nv_bfloat162 L0, L1;
        L0.x = __float2bfloat16(x.x - __bfloat162float(h0));
        L0.y = __float2bfloat16(x.y - __bfloat162float(h1));
        L1.x = __float2bfloat16(x.z - __bfloat162float(h2));
        L1.y = __float2bfloat16(x.w - __bfloat162float(h3));
        *(__nv_bfloat162*)(lo + i)     = L0;
        *(__nv_bfloat162*)(lo + i + 2) = L1;
    }
}

// =================================================================
// split-bf16 tensor GEMM (mma.sync HMMA path) + fused eval BN.
// C[m][n] = bn( A[m,:]·W[n,:] ),  A=Ahi+Alo, W=Whi+Wlo,
// C ≈ Ahi·Whi + Ahi·Wlo + Alo·Whi, fp32 reg accumulation across
// all 3 passes.  CTA tile 128x128; 8 warps = 2(m) x 4(n), warp
// tile 64x32 via m16n8k16.  K in 64-elem SW128 slabs (cp.async.cg,
// zero-fill M tail).  Both A and W are k-contiguous -> both frags
// via NON-transposed ldmatrix.
// =================================================================
__global__ void __launch_bounds__(256) tc_gemm_kernel(
    const __nv_bfloat16* __restrict__ Ahi, const __nv_bfloat16* __restrict__ Alo,
    const __nv_bfloat16* __restrict__ Whi, const __nv_bfloat16* __restrict__ Wlo,
    float* __restrict__ C,
    const float* __restrict__ gam, const float* __restrict__ bet,
    const float* __restrict__ mu,  const float* __restrict__ var,
    int K, int Mtot)
{
    __shared__ __align__(128) __nv_bfloat16 As[128*64];   // 16 KB, SW128 rows
    __shared__ __align__(128) __nv_bfloat16 Bs[128*64];   // 16 KB
    __shared__ float s_sc[128], s_sh[128];

    uint32_t a_s = smem_u32(As);
    uint32_t b_s = smem_u32(Bs);

    int tid  = threadIdx.x;
    int w    = tid >> 5, lane = tid & 31;
    int wm   = w & 1;            // m half (64 rows)
    int wn   = w >> 1;           // n quarter (32 cols)
    int m0   = blockIdx.y * 128;
    int n0   = blockIdx.x * 128;

    if (tid < 128) {
        int n = n0 + tid;
        float inv = rsqrtf(var[n] + EPSF);
        float sc = gam[n] * inv;
        s_sc[tid] = sc;
        s_sh[tid] = bet[n] - mu[n] * sc;
    }

    float acc[4][4][4];
    #pragma unroll
    for (int i = 0; i < 4; i++)
        #pragma unroll
        for (int j = 0; j < 4; j++)
            #pragma unroll
            for (int q = 0; q < 4; q++) acc[i][j][q] = 0.f;

    // ldmatrix lane addresses (fixed per thread, k-step offset added later)
    // A frag i: row = wm*64 + i*16 + (lane&15), kb = (lane>>4)*16
    // B frag j: row = wn*32 + j*8  + (lane&7),  kb = ((lane>>3)&1)*16
    uint32_t a_off0 = (uint32_t)((wm*64 + (lane & 15)) << 7) + ((lane >> 4) << 4);
    uint32_t b_off0 = (uint32_t)((wn*32 + (lane & 7)) << 7) + (((lane >> 3) & 1) << 4);

    int nslab = K >> 6;

    for (int pass = 0; pass < 3; pass++) {
        const __nv_bfloat16* Ap = (pass == 2) ? Alo : Ahi;
        const __nv_bfloat16* Bp = (pass == 1) ? Wlo : Whi;
        for (int ks = 0; ks < nslab; ks++) {
            // ---- stage slab: 2048 x 16B granules, 8 per thread ----
            #pragma unroll
            for (int i = 0; i < 4; i++) {
                int idx = tid + (i << 8);
                int r = idx >> 3, g = idx & 7;
                uint32_t dsw = SMEM_SWZ((uint32_t)((r << 7) + (g << 4)));
                int arow = m0 + r;
                int sz = (arow < Mtot) ? 16 : 0;
                if (arow >= Mtot) arow = Mtot - 1;
                const __nv_bfloat16* sa = Ap + (size_t)arow*K + (ks << 6) + (g << 3);
                asm volatile("cp.async.cg.shared.global [%0], [%1], 16, %2;"
                             :: "r"(a_s + dsw), "l"(sa), "r"(sz) : "memory");
                const __nv_bfloat16* sb = Bp + (size_t)(n0 + r)*K + (ks << 6) + (g << 3);
                asm volatile("cp.async.cg.shared.global [%0], [%1], 16;"
                             :: "r"(b_s + dsw), "l"(sb) : "memory");
            }
            CPA_COMMIT();
            CPA_WAIT(0);
            __syncthreads();

            // ---- compute slab: 4 k-steps of 16 ----
            #pragma unroll
            for (int kst = 0; kst < 4; kst++) {
                uint32_t af[4][4], bf[4][2];
                #pragma unroll
                for (int i = 0; i < 4; i++) {
                    uint32_t off = a_off0 + (uint32_t)(i << 11) + (uint32_t)(kst << 5);
                    LDSM_X4(af[i][0], af[i][1], af[i][2], af[i][3], a_s + SMEM_SWZ(off));
                }
                #pragma unroll
                for (int j = 0; j < 4; j++) {
                    uint32_t off = b_off0 + (uint32_t)(j << 10) + (uint32_t)(kst << 5);
                    LDSM_X2(bf[j][0], bf[j][1], b_s + SMEM_SWZ(off));
                }
                #pragma unroll
                for (int i = 0; i < 4; i++)
                    #pragma unroll
                    for (int j = 0; j < 4; j++)
                        MMA16816(acc[i][j], af[i], bf[j]);
            }
            __syncthreads();
        }
    }

    // ---- epilogue: BN + store from register accumulators ----
    #pragma unroll
    for (int i = 0; i < 4; i++) {
        int r0 = m0 + wm*64 + i*16 + (lane >> 2);
        #pragma unroll
        for (int j = 0; j < 4; j++) {
            int c = wn*32 + j*8 + 2*(lane & 3);
            float sc0 = s_sc[c], sc1 = s_sc[c+1];
            float sh0 = s_sh[c], sh1 = s_sh[c+1];
            if (r0 < Mtot) {
                float2 v;
                v.x = acc[i][j][0] * sc0 + sh0;
                v.y = acc[i][j][1] * sc1 + sh1;
                *(float2*)(C + (size_t)r0*HH + n0 + c) = v;
            }
            if (r0 + 8 < Mtot) {
                float2 v;
                v.x = acc[i][j][2] * sc0 + sh0;
                v.y = acc[i][j][3] * sc1 + sh1;
                *(float2*)(C + (size_t)(r0+8)*HH + n0 + c) = v;
            }
        }
    }
}

// =================================================================
// persistent liGRU scan (R9 version, frozen: 6.04ms/layer).
// =================================================================
__global__ void __launch_bounds__(256, 1) scan_kernel(
    const float* __restrict__ WH, const float* __restrict__ WZ,
    const float* __restrict__ Uh, const float* __restrict__ Uz,
    float* __restrict__ Hout, float* __restrict__ hT,
    int* __restrict__ flags)
{
    extern __shared__ float smem[];
    float* hs  = smem;                       // [16][1024]
    u64*   red = (u64*)(smem + BB*HH);       // [128][REDS]

    int tid = threadIdx.x;
    int qd  = tid >> 7;
    int bh  = (tid >> 6) & 1;
    int kg  = tid & 63;
    int j0  = blockIdx.x * 8;

    u64 uz[2][16], uh[2][16];
    #pragma unroll
    for (int pr = 0; pr < 2; pr++) {
        const float* z0 = Uz + (size_t)(j0 + qd*4 + 2*pr)*HH;
        const float* z1 = z0 + HH;
        const float* a0 = Uh + (size_t)(j0 + qd*4 + 2*pr)*HH;
        const float* a1 = a0 + HH;
        #pragma unroll
        for (int kk = 0; kk < 16; kk++) {
            int k = kg + (kk << 6);
            PACK2(uz[pr][kk], z0[k], z1[k]);
            PACK2(uh[pr][kk], a0[k], a1[k]);
        }
    }
    for (int idx = tid; idx < BB*HH; idx += 256) hs[idx] = 0.f;
    __syncthreads();

    int r_b   = tid & 15;
    int r_grp = tid >> 4;
    int r_m   = r_grp & 1;
    int g_qd  = (r_grp >> 2) & 1;
    int g_pr  = (r_grp >> 1) & 1;
    int jg    = j0 + g_qd*4 + g_pr*2;
    bool is_red  = (tid < 128);
    bool is_gate = is_red && (r_m == 0);

    for (int t = 0; t < TT; t++) {
        float2 wz2 = make_float2(0.f, 0.f), wh2 = wz2;
        size_t ob = 0;
        if (is_gate) {
            ob = ((size_t)t*BB + r_b)*HH + jg;
            wz2 = *(const float2*)(WZ + ob);
            wh2 = *(const float2*)(WH + ob);
        }

        u64 az[2][8], ah[2][8];
        #pragma unroll
        for (int pr = 0; pr < 2; pr++)
            #pragma unroll
            for (int b = 0; b < 8; b++) { az[pr][b] = 0ull; ah[pr][b] = 0ull; }

        const float* hb = hs + (bh << 3)*HH + kg;

        CPA_WAIT(1);
        __syncthreads();
        #pragma unroll
        for (int kk = 0; kk < 8; kk++) {
            const float* hk = hb + (kk << 6);
            #pragma unroll
            for (int b = 0; b < 8; b++) {
                float hv = hk[b*HH];
                u64 hd; PACK2(hd, hv, hv);
                FMA2(az[0][b], hd, uz[0][kk], az[0][b]);
                FMA2(ah[0][b], hd, uh[0][kk], ah[0][b]);
                FMA2(az[1][b], hd, uz[1][kk], az[1][b]);
                FMA2(ah[1][b], hd, uh[1][kk], ah[1][b]);
            }
        }
        CPA_WAIT(0);
        __syncthreads();
        #pragma unroll
        for (int kk = 8; kk < 16; kk++) {
            const float* hk = hb + (kk << 6);
            #pragma unroll
            for (int b = 0; b < 8; b++) {
                float hv = hk[b*HH];
                u64 hd; PACK2(hd, hv, hv);
                FMA2(az[0][b], hd, uz[0][kk], az[0][b]);
                FMA2(ah[0][b], hd, uh[0][kk], ah[0][b]);
                FMA2(az[1][b], hd, uz[1][kk], az[1][b]);
                FMA2(ah[1][b], hd, uh[1][kk], ah[1][b]);
            }
        }

        {
            u64* rp = red + kg;
            #pragma unroll
            for (int pr = 0; pr < 2; pr++)
                #pragma unroll
                for (int b = 0; b < 8; b++) {
                    int bb = (bh << 3) + b;
                    rp[((qd*4 + pr*2    )*16 + bb)*REDS] = az[pr][b];
                    rp[((qd*4 + pr*2 + 1)*16 + bb)*REDS] = ah[pr][b];
                }
        }
        __syncthreads();

        if (is_red) {
            const u64* rr = red + (size_t)tid*REDS;
            u64 s0 = 0ull, s1 = 0ull, s2 = 0ull, s3 = 0ull;
            #pragma unroll
            for (int i = 0; i < 64; i += 4) {
                ADD2(s0, s0, rr[i]);
                ADD2(s1, s1, rr[i+1]);
                ADD2(s2, s2, rr[i+2]);
                ADD2(s3, s3, rr[i+3]);
            }
            ADD2(s0, s0, s1);
            ADD2(s2, s2, s3);
            ADD2(s0, s0, s2);
            u64 part = __shfl_xor_sync(0xffffffffu, s0, 16);
            if (is_gate) {
                float z0, z1, a0, a1;
                UNPACK2(z0, z1, s0);
                UNPACK2(a0, a1, part);
                float zt0 = 1.f / (1.f + __expf(-(wz2.x + z0)));
                float zt1 = 1.f / (1.f + __expf(-(wz2.y + z1)));
                float hc0 = fmaxf(wh2.x + a0, 0.f) * KEEPF;
                float hc1 = fmaxf(wh2.y + a1, 0.f) * KEEPF;
                float2 ho = *(const float2*)(hs + r_b*HH + jg);
                float2 hn;
                hn.x = zt0*ho.x + (1.f - zt0)*hc0;
                hn.y = zt1*ho.y + (1.f - zt1)*hc1;
                *(float2*)(Hout + ob)        = hn;
                *(float2*)(hT + r_b*HH + jg) = hn;
            }
        }
        __syncthreads();
        if (t == TT-1) break;

        if (tid == 0) {
            asm volatile("st.release.gpu.global.s32 [%0], %1;"
                         :: "l"(flags + blockIdx.x*FPAD), "r"(t+1) : "memory");
        }
        if (tid < GRID_SCAN) {
            const int* fp = flags + tid*FPAD;
            int v;
            do {
                asm volatile("ld.acquire.gpu.global.s32 %0, [%1];"
                             : "=r"(v) : "l"(fp) : "memory");
            } while (v <= t);
        }
        __syncthreads();

        {
            #pragma unroll
            for (int i = 0; i < 8; i++) {
                int idx = i*256 + tid;
                int b = idx >> 7, c = idx & 127;
                const float* src = hT + b*HH + (c << 2);
                unsigned dst = (unsigned)__cvta_generic_to_shared(hs + b*HH + (c << 2));
                asm volatile("cp.async.cg.shared.global [%0], [%1], 16;"
                             :: "r"(dst), "l"(src) : "memory");
            }
            CPA_COMMIT();
            #pragma unroll
            for (int i = 0; i < 8; i++) {
                int idx = i*256 + tid;
                int b = idx >> 7, c = (idx & 127) + 128;
                const float* src = hT + b*HH + (c << 2);
                unsigned dst = (unsigned)__cvta_generic_to_shared(hs + b*HH + (c << 2));
                asm volatile("cp.async.cg.shared.global [%0], [%1], 16;"
                             :: "r"(dst), "l"(src) : "memory");
            }
            CPA_COMMIT();
        }
    }
}

// =================================================================
extern "C" void kernel_launch(void* const* d_in, const int* in_sizes, int n_in,
                              void* d_out, int out_size)
{
    const float* x     = (const float*)d_in[0];
    const int*   x_len = (const int*)  d_in[1];
    const float* whW0  = (const float*)d_in[2];
    const float* wzW0  = (const float*)d_in[3];
    const float* uhW0  = (const float*)d_in[4];
    const float* uzW0  = (const float*)d_in[5];
    const float* bnh_g0 = (const float*)d_in[6];
    const float* bnh_b0 = (const float*)d_in[7];
    const float* bnh_m0 = (const float*)d_in[8];
    const float* bnh_v0 = (const float*)d_in[9];
    const float* bnz_g0 = (const float*)d_in[10];
    const float* bnz_b0 = (const float*)d_in[11];
    const float* bnz_m0 = (const float*)d_in[12];
    const float* bnz_v0 = (const float*)d_in[13];
    const float* whW1  = (const float*)d_in[14];
    const float* wzW1  = (const float*)d_in[15];
    const float* uhW1  = (const float*)d_in[16];
    const float* uzW1  = (const float*)d_in[17];
    const float* bnh_g1 = (const float*)d_in[18];
    const float* bnh_b1 = (const float*)d_in[19];
    const float* bnh_m1 = (const float*)d_in[20];
    const float* bnh_v1 = (const float*)d_in[21];
    const float* bnz_g1 = (const float*)d_in[22];
    const float* bnz_b1 = (const float*)d_in[23];
    const float* bnz_m1 = (const float*)d_in[24];
    const float* bnz_v1 = (const float*)d_in[25];

    float* out = (float*)d_out;

    float *p_wh, *p_wz, *p_h0, *p_hT; int* p_fl;
    __nv_bfloat16 *p_ahi, *p_alo, *p_whi, *p_wlo;
    cudaGetSymbolAddress((void**)&p_wh, g_wh);
    cudaGetSymbolAddress((void**)&p_wz, g_wz);
    cudaGetSymbolAddress((void**)&p_h0, g_h0);
    cudaGetSymbolAddress((void**)&p_hT, g_hT);
    cudaGetSymbolAddress((void**)&p_fl, g_flags);
    cudaGetSymbolAddress((void**)&p_ahi, g_ahi);
    cudaGetSymbolAddress((void**)&p_alo, g_alo);
    cudaGetSymbolAddress((void**)&p_whi, g_whi);
    cudaGetSymbolAddress((void**)&p_wlo, g_wlo);

    int smem_scan = BB*HH*(int)sizeof(float) + 128*REDS*(int)sizeof(u64); // 132096
    cudaFuncSetAttribute(scan_kernel,
        cudaFuncAttributeMaxDynamicSharedMemorySize, smem_scan);

    init_kernel<<<32, 256>>>(x_len, out, out_size);

    dim3 gg(HH/128, MTILES);     // (8, 188)

    // ---- layer 0 (K = 512) ----
    split_kernel<<<592, 256>>>(x, p_ahi, p_alo, MTOT*DD);
    split_kernel<<<592, 256>>>(whW0, p_whi, p_wlo, HH*DD);
    tc_gemm_kernel<<<gg, 256>>>(p_ahi, p_alo, p_whi, p_wlo, p_wh,
                                bnh_g0, bnh_b0, bnh_m0, bnh_v0, DD, MTOT);
    split_kernel<<<592, 256>>>(wzW0, p_whi, p_wlo, HH*DD);
    tc_gemm_kernel<<<gg, 256>>>(p_ahi, p_alo, p_whi, p_wlo, p_wz,
                                bnz_g0, bnz_b0, bnz_m0, bnz_v0, DD, MTOT);
    scan_kernel<<<GRID_SCAN, 256, smem_scan>>>(p_wh, p_wz, uhW0, uzW0, p_h0, p_hT, p_fl);

    // ---- layer 1 (K = 1024) ----
    split_kernel<<<592, 256>>>(p_h0, p_ahi, p_alo, MTOT*HH);
    split_kernel<<<592, 256>>>(whW1, p_whi, p_wlo, HH*HH);
    tc_gemm_kernel<<<gg, 256>>>(p_ahi, p_alo, p_whi, p_wlo, p_wh,
                                bnh_g1, bnh_b1, bnh_m1, bnh_v1, HH, MTOT);
    split_kernel<<<592, 256>>>(wzW1, p_whi, p_wlo, HH*HH);
    tc_gemm_kernel<<<gg, 256>>>(p_ahi, p_alo, p_whi, p_wlo, p_wz,
                                bnz_g1, bnz_b1, bnz_m1, bnz_v1, HH, MTOT);
    scan_kernel<<<GRID_SCAN, 256, smem_scan>>>(p_wh, p_wz, uhW1, uzW1, out, p_hT,
                                               p_fl + GRID_SCAN*FPAD);
}